// round 2
// baseline (speedup 1.0000x reference)
#include <cuda_runtime.h>
#include <cstdint>

#define Bdim 16
#define L 256
#define H 256

typedef unsigned long long ull;

// Scratch (device globals: allocation-free)
__device__ float g_A[Bdim * L * H];    // A[b][q][o] row-major (= query @ Wq^T)
__device__ float g_Ct2[Bdim * L * H];  // [b][op=o/2][c][2] : C[b][c][o], C = context @ Wc^T + bias

// ---------------- f32x2 helpers ----------------
__device__ __forceinline__ ull fma2(ull a, ull b, ull c) {
    ull d; asm("fma.rn.f32x2 %0, %1, %2, %3;" : "=l"(d) : "l"(a), "l"(b), "l"(c)); return d;
}
__device__ __forceinline__ ull add2(ull a, ull b) {
    ull d; asm("add.rn.f32x2 %0, %1, %2;" : "=l"(d) : "l"(a), "l"(b)); return d;
}
__device__ __forceinline__ ull pack2(float lo, float hi) {
    ull d; asm("mov.b64 %0, {%1, %2};" : "=l"(d) : "f"(lo), "f"(hi)); return d;
}
__device__ __forceinline__ float2 unpack2(ull a) {
    float2 r; asm("mov.b64 {%0, %1}, %2;" : "=f"(r.x), "=f"(r.y) : "l"(a)); return r;
}
__device__ __forceinline__ float hsum2(ull a) { float2 r = unpack2(a); return r.x + r.y; }

// ---------------- Projection GEMM ----------------
// z=0: A[row][o] = sum_h query[row][h] * W[o][h]
// z=1: C[row][o] = sum_h context[row][h] * W[o][256+h] + bias[o], stored transposed-interleaved
#define KC 32
#define PAD 70

__global__ __launch_bounds__(256) void proj_kernel(
    const float* __restrict__ query, const float* __restrict__ context,
    const float* __restrict__ W, const float* __restrict__ bias)
{
    __shared__ __align__(16) float smem_all[2 * KC * PAD];
    float (*As)[PAD] = (float(*)[PAD])smem_all;            // As[k][m]
    float (*Bs)[PAD] = (float(*)[PAD])(smem_all + KC * PAD); // Bs[k][n]

    const int tid = threadIdx.x;
    const int tx = tid & 15;          // n quad
    const int ty = tid >> 4;          // m quad
    const int row0 = blockIdx.x * 64;
    const int n0 = blockIdx.y * 64;
    const int which = blockIdx.z;

    const float* X = which ? context : query;
    const float* Wbase = W + (which ? H : 0);   // row stride 2H

    ull acc[4][2];
    #pragma unroll
    for (int i = 0; i < 4; i++) { acc[i][0] = 0ULL; acc[i][1] = 0ULL; }

    for (int kc = 0; kc < H; kc += KC) {
        // stage X tile (coalesced read, 2-way-conflict smem store)
        #pragma unroll
        for (int it = 0; it < 8; it++) {
            int i = it * 256 + tid;
            int r = i >> 5, k = i & 31;
            As[k][r] = X[(row0 + r) * H + kc + k];
        }
        // stage W tile
        #pragma unroll
        for (int it = 0; it < 8; it++) {
            int i = it * 256 + tid;
            int n = i >> 5, k = i & 31;
            Bs[k][n] = Wbase[(n0 + n) * (2 * H) + kc + k];
        }
        __syncthreads();

        #pragma unroll
        for (int k = 0; k < KC; k++) {
            ull b01 = *(const ull*)&Bs[k][tx * 4];
            ull b23 = *(const ull*)&Bs[k][tx * 4 + 2];
            #pragma unroll
            for (int i = 0; i < 4; i++) {
                float a = As[k][ty * 4 + i];
                ull a2 = pack2(a, a);
                acc[i][0] = fma2(a2, b01, acc[i][0]);
                acc[i][1] = fma2(a2, b23, acc[i][1]);
            }
        }
        __syncthreads();
    }

    if (which == 0) {
        // write A row-major, STG.128
        #pragma unroll
        for (int i = 0; i < 4; i++) {
            float2 p0 = unpack2(acc[i][0]);
            float2 p1 = unpack2(acc[i][1]);
            float4 v = make_float4(p0.x, p0.y, p1.x, p1.y);
            *(float4*)&g_A[(row0 + ty * 4 + i) * H + n0 + tx * 4] = v;
        }
    } else {
        // add bias, transpose via smem, write Ct2 interleaved-pair layout
        float bv0 = bias[n0 + tx * 4 + 0];
        float bv1 = bias[n0 + tx * 4 + 1];
        float bv2v = bias[n0 + tx * 4 + 2];
        float bv3 = bias[n0 + tx * 4 + 3];
        float* T = smem_all;  // 64 x 66 tile fits in 2*KC*PAD = 4480 floats
        #pragma unroll
        for (int i = 0; i < 4; i++) {
            float2 p0 = unpack2(acc[i][0]);
            float2 p1 = unpack2(acc[i][1]);
            int m = ty * 4 + i;
            T[m * 66 + tx * 4 + 0] = p0.x + bv0;
            T[m * 66 + tx * 4 + 1] = p0.y + bv1;
            T[m * 66 + tx * 4 + 2] = p1.x + bv2v;
            T[m * 66 + tx * 4 + 3] = p1.y + bv3;
        }
        __syncthreads();
        const int b = row0 >> 8;
        const int c0 = row0 & 255;
        float2* dst = (float2*)g_Ct2;
        #pragma unroll
        for (int it = 0; it < 8; it++) {
            int e = it * 256 + tid;
            int m = e & 63;        // c within tile
            int np = e >> 6;       // o-pair within tile (0..31)
            float v0 = T[m * 66 + 2 * np];
            float v1 = T[m * 66 + 2 * np + 1];
            dst[(b * 128 + (n0 >> 1) + np) * 256 + (c0 + m)] = make_float2(v0, v1);
        }
    }
}

// ---------------- Fused score + softmax + AV ----------------
// block: 256 threads, handles (b, q0..q0+7). thread = c (score phase) / h (AV phase).
__global__ __launch_bounds__(256) void score_kernel(
    const float* __restrict__ ctx, const int* __restrict__ mask,
    const float* __restrict__ sw, float* __restrict__ attn_out, float* __restrict__ attn)
{
    __shared__ __align__(16) float Aq[8][258];
    __shared__ __align__(16) float S[8][256];
    __shared__ __align__(16) ull v2s[128];
    __shared__ __align__(16) ull bv2s[128];
    __shared__ float sq_s[8], mx_s[8], inv_s[8];

    const int tid = threadIdx.x;
    const int lane = tid & 31;
    const int w = tid >> 5;
    const int b = blockIdx.x >> 5;
    const int q0 = (blockIdx.x & 31) << 3;

    if (tid < 128) {
        float va = sw[2 * tid], vb = sw[2 * tid + 1];
        v2s[tid] = pack2(va, vb);
        bv2s[tid] = pack2(0.495f * va, 0.495f * vb);
    }
    #pragma unroll
    for (int it = 0; it < 8; it++) {
        int i = it * 256 + tid;
        int q = i >> 8, o = i & 255;
        Aq[q][o] = g_A[(b * L + q0 + q) * H + o];
    }
    __syncthreads();

    // sq[q] = sum_o v[o] * A[q][o]   (warp w handles q = w)
    {
        float s = 0.f;
        #pragma unroll
        for (int j = 0; j < 8; j++) s += sw[lane + 32 * j] * Aq[w][lane + 32 * j];
        #pragma unroll
        for (int off = 16; off; off >>= 1) s += __shfl_xor_sync(0xffffffffu, s, off);
        if (lane == 0) sq_s[w] = s;
    }

    // main score loop: thread t = column c = tid
    ull acc[8];
    #pragma unroll
    for (int q = 0; q < 8; q++) acc[q] = 0ULL;
    ull lin = 0ULL;
    const float2* Ct = (const float2*)g_Ct2 + b * (128 * 256) + tid;
    const ull ABSM = 0x7FFFFFFF7FFFFFFFULL;
    #pragma unroll 2
    for (int op = 0; op < 128; op++) {
        float2 cf = Ct[op * 256];
        ull c2; asm("mov.b64 %0, {%1, %2};" : "=l"(c2) : "f"(cf.x), "f"(cf.y));
        ull vv = v2s[op];
        ull bb = bv2s[op];
        lin = fma2(c2, vv, lin);
        #pragma unroll
        for (int q = 0; q < 8; q++) {
            ull a2 = *(const ull*)&Aq[q][2 * op];
            ull t = add2(a2, c2);
            t &= ABSM;
            acc[q] = fma2(t, bb, acc[q]);
        }
    }
    __syncthreads();   // sq_s ready

    float sc = hsum2(lin);
    int mk = mask[b * L + tid];
    const float NEG_INF = __int_as_float(0xff800000u);
    #pragma unroll
    for (int q = 0; q < 8; q++) {
        float s = 0.505f * (sq_s[q] + sc) + hsum2(acc[q]);
        if (mk == 0) s = NEG_INF;
        S[q][tid] = s;
    }
    __syncthreads();

    // softmax: warp w reduces row q = w
    {
        float m = NEG_INF;
        #pragma unroll
        for (int j = 0; j < 8; j++) m = fmaxf(m, S[w][lane + 32 * j]);
        #pragma unroll
        for (int off = 16; off; off >>= 1) m = fmaxf(m, __shfl_xor_sync(0xffffffffu, m, off));
        float ssum = 0.f;
        #pragma unroll
        for (int j = 0; j < 8; j++) {
            float e = __expf(S[w][lane + 32 * j] - m);
            S[w][lane + 32 * j] = e;
            ssum += e;
        }
        #pragma unroll
        for (int off = 16; off; off >>= 1) ssum += __shfl_xor_sync(0xffffffffu, ssum, off);
        if (lane == 0) { mx_s[w] = m; inv_s[w] = 1.f / ssum; }
    }
    __syncthreads();

    // scale + write attn
    #pragma unroll
    for (int q = 0; q < 8; q++) {
        float a = S[q][tid] * inv_s[q];
        S[q][tid] = a;
        attn[(b * L + q0 + q) * L + tid] = a;
    }
    __syncthreads();

    // AV: out[q][h=tid] = sum_c attn[q][c] * ctx[b][c][h], c packed in pairs
    ull av[8];
    #pragma unroll
    for (int q = 0; q < 8; q++) av[q] = 0ULL;
    const float* cb = ctx + b * (L * H) + tid;
    #pragma unroll 2
    for (int cp = 0; cp < 128; cp++) {
        float x0 = cb[(2 * cp) * H];
        float x1 = cb[(2 * cp + 1) * H];
        ull c2 = pack2(x0, x1);
        #pragma unroll
        for (int q = 0; q < 8; q++) {
            ull a2 = *(const ull*)&S[q][2 * cp];
            av[q] = fma2(a2, c2, av[q]);
        }
    }
    #pragma unroll
    for (int q = 0; q < 8; q++) {
        attn_out[(b * L + q0 + q) * H + tid] = hsum2(av[q]);
    }
}

extern "C" void kernel_launch(void* const* d_in, const int* in_sizes, int n_in,
                              void* d_out, int out_size)
{
    const float* query   = (const float*)d_in[0];
    const float* context = (const float*)d_in[1];
    const int*   mask    = (const int*)d_in[2];
    const float* w       = (const float*)d_in[3];
    const float* bias    = (const float*)d_in[4];
    const float* sw      = (const float*)d_in[5];

    float* out = (float*)d_out;
    float* attn_out = out;                      // (B, Lq, H)
    float* attn     = out + Bdim * L * H;       // (B, Lq, Lc)

    dim3 pgrid(64, 4, 2);
    proj_kernel<<<pgrid, 256>>>(query, context, w, bias);
    score_kernel<<<512, 256>>>(context, mask, sw, attn_out, attn);
}

// round 4
// speedup vs baseline: 1.2331x; 1.2331x over previous
#include <cuda_runtime.h>
#include <cstdint>

#define Bdim 16
#define L 256
#define H 256

typedef unsigned long long ull;

// Scratch (device globals: allocation-free)
__device__ __align__(16) float g_A[Bdim * L * H];    // A[b][q][o] row-major (= query @ Wq^T)
__device__ __align__(16) float g_Ct2[Bdim * L * H];  // [b][op=o/2][c][2] : C[b][c][o], C = context @ Wc^T + bias

// ---------------- f32x2 helpers ----------------
__device__ __forceinline__ ull fma2(ull a, ull b, ull c) {
    ull d; asm("fma.rn.f32x2 %0, %1, %2, %3;" : "=l"(d) : "l"(a), "l"(b), "l"(c)); return d;
}
__device__ __forceinline__ ull add2(ull a, ull b) {
    ull d; asm("add.rn.f32x2 %0, %1, %2;" : "=l"(d) : "l"(a), "l"(b)); return d;
}
__device__ __forceinline__ ull pack2(float lo, float hi) {
    ull d; asm("mov.b64 %0, {%1, %2};" : "=l"(d) : "f"(lo), "f"(hi)); return d;
}
__device__ __forceinline__ float2 unpack2(ull a) {
    float2 r; asm("mov.b64 {%0, %1}, %2;" : "=f"(r.x), "=f"(r.y) : "l"(a)); return r;
}
__device__ __forceinline__ float hsum2(ull a) { float2 r = unpack2(a); return r.x + r.y; }

// ---------------- Projection GEMM ----------------
// z=0: A[row][o] = sum_h query[row][h] * W[o][h]
// z=1: C[row][o] = sum_h context[row][h] * W[o][256+h] + bias[o], stored transposed-interleaved
#define KC 32
#define PAD 70

__global__ __launch_bounds__(256) void proj_kernel(
    const float* __restrict__ query, const float* __restrict__ context,
    const float* __restrict__ W, const float* __restrict__ bias)
{
    __shared__ __align__(16) float smem_all[2 * KC * PAD];
    float (*As)[PAD] = (float(*)[PAD])smem_all;              // As[k][m]
    float (*Bs)[PAD] = (float(*)[PAD])(smem_all + KC * PAD); // Bs[k][n]

    const int tid = threadIdx.x;
    const int tx = tid & 15;          // n quad
    const int ty = tid >> 4;          // m quad
    const int row0 = blockIdx.x * 64;
    const int n0 = blockIdx.y * 64;
    const int which = blockIdx.z;

    const float* X = which ? context : query;
    const float* Wbase = W + (which ? H : 0);   // row stride 2H

    ull acc[4][2];
    #pragma unroll
    for (int i = 0; i < 4; i++) { acc[i][0] = 0ULL; acc[i][1] = 0ULL; }

    for (int kc = 0; kc < H; kc += KC) {
        #pragma unroll
        for (int it = 0; it < 8; it++) {
            int i = it * 256 + tid;
            int r = i >> 5, k = i & 31;
            As[k][r] = X[(row0 + r) * H + kc + k];
        }
        #pragma unroll
        for (int it = 0; it < 8; it++) {
            int i = it * 256 + tid;
            int n = i >> 5, k = i & 31;
            Bs[k][n] = Wbase[(n0 + n) * (2 * H) + kc + k];
        }
        __syncthreads();

        #pragma unroll
        for (int k = 0; k < KC; k++) {
            ull b01 = *(const ull*)&Bs[k][tx * 4];
            ull b23 = *(const ull*)&Bs[k][tx * 4 + 2];
            #pragma unroll
            for (int i = 0; i < 4; i++) {
                float a = As[k][ty * 4 + i];
                ull a2 = pack2(a, a);
                acc[i][0] = fma2(a2, b01, acc[i][0]);
                acc[i][1] = fma2(a2, b23, acc[i][1]);
            }
        }
        __syncthreads();
    }

    if (which == 0) {
        #pragma unroll
        for (int i = 0; i < 4; i++) {
            float2 p0 = unpack2(acc[i][0]);
            float2 p1 = unpack2(acc[i][1]);
            float4 v = make_float4(p0.x, p0.y, p1.x, p1.y);
            *(float4*)&g_A[(row0 + ty * 4 + i) * H + n0 + tx * 4] = v;
        }
    } else {
        float bv0 = bias[n0 + tx * 4 + 0];
        float bv1 = bias[n0 + tx * 4 + 1];
        float bv2v = bias[n0 + tx * 4 + 2];
        float bv3 = bias[n0 + tx * 4 + 3];
        float* T = smem_all;  // 64 x 66 tile
        #pragma unroll
        for (int i = 0; i < 4; i++) {
            float2 p0 = unpack2(acc[i][0]);
            float2 p1 = unpack2(acc[i][1]);
            int m = ty * 4 + i;
            T[m * 66 + tx * 4 + 0] = p0.x + bv0;
            T[m * 66 + tx * 4 + 1] = p0.y + bv1;
            T[m * 66 + tx * 4 + 2] = p1.x + bv2v;
            T[m * 66 + tx * 4 + 3] = p1.y + bv3;
        }
        __syncthreads();
        const int b = row0 >> 8;
        const int c0 = row0 & 255;
        float2* dst = (float2*)g_Ct2;
        #pragma unroll
        for (int it = 0; it < 8; it++) {
            int e = it * 256 + tid;
            int m = e & 63;        // c within tile
            int np = e >> 6;       // o-pair within tile (0..31)
            float v0 = T[m * 66 + 2 * np];
            float v1 = T[m * 66 + 2 * np + 1];
            dst[(b * 128 + (n0 >> 1) + np) * 256 + (c0 + m)] = make_float2(v0, v1);
        }
    }
}

// ---------------- Fused score + softmax + AV ----------------
// block: 256 threads, (b, q0..q0+7). Score loop: tg = tid>>7 picks q-half,
// ct = tid&127 picks the c-pair (2ct, 2ct+1). One LDG.128 = (c,c+1)x(o,o+1).
__global__ __launch_bounds__(256, 4) void score_kernel(
    const float* __restrict__ ctx, const int* __restrict__ mask,
    const float* __restrict__ sw, float* __restrict__ attn_out, float* __restrict__ attn)
{
    __shared__ __align__(16) float Aq[8][256];
    __shared__ __align__(16) float S[8][256];
    __shared__ __align__(16) ull v2s[128];
    __shared__ float sq_s[8], inv_s[8];

    const int tid = threadIdx.x;
    const int lane = tid & 31;
    const int w = tid >> 5;
    const int b = blockIdx.x >> 5;
    const int q0 = (blockIdx.x & 31) << 3;
    const int tg = tid >> 7;
    const int ct = tid & 127;
    const int c0 = ct << 1;

    if (tid < 128) v2s[tid] = pack2(sw[2 * tid], sw[2 * tid + 1]);
    #pragma unroll
    for (int it = 0; it < 2; it++) {
        int i = it * 256 + tid;
        int q = i >> 6, o = (i & 63) << 2;
        *(float4*)&Aq[q][o] = *(const float4*)&g_A[(b * L + q0 + q) * H + o];
    }
    __syncthreads();

    // sq[q] = sum_o v[o] * A[q][o]   (warp w handles q = w)
    {
        float s = 0.f;
        #pragma unroll
        for (int j = 0; j < 8; j++) s += sw[lane + 32 * j] * Aq[w][lane + 32 * j];
        #pragma unroll
        for (int off = 16; off; off >>= 1) s += __shfl_xor_sync(0xffffffffu, s, off);
        if (lane == 0) sq_s[w] = s;
    }

    // main score loop
    ull acc[4][2];
    #pragma unroll
    for (int q = 0; q < 4; q++) { acc[q][0] = 0ULL; acc[q][1] = 0ULL; }
    ull lin0 = 0ULL, lin1 = 0ULL;
    const float4* Ct4 = (const float4*)g_Ct2 + b * (128 * 128) + ct;
    const ull ABSM = 0x7FFFFFFF7FFFFFFFULL;

    float4 pA = Ct4[0];
    float4 pB = Ct4[128];
    #pragma unroll 2
    for (int og = 0; og < 64; og++) {
        float4 cA = pA, cB = pB;
        int nog = (og + 1) & 63;
        pA = Ct4[(2 * nog) * 128];
        pB = Ct4[(2 * nog) * 128 + 128];
        ull c00 = pack2(cA.x, cA.y);   // c0, o-pair even
        ull c10 = pack2(cA.z, cA.w);   // c1, o-pair even
        ull c01 = pack2(cB.x, cB.y);   // c0, o-pair odd
        ull c11 = pack2(cB.z, cB.w);   // c1, o-pair odd
        ulonglong2 vv = *(const ulonglong2*)&v2s[2 * og];
        lin0 = fma2(c00, vv.x, lin0); lin0 = fma2(c01, vv.y, lin0);
        lin1 = fma2(c10, vv.x, lin1); lin1 = fma2(c11, vv.y, lin1);
        #pragma unroll
        for (int q = 0; q < 4; q++) {
            ulonglong2 a2 = *(const ulonglong2*)&Aq[tg * 4 + q][og << 2];
            ull t;
            t = add2(a2.x, c00) & ABSM; acc[q][0] = fma2(t, vv.x, acc[q][0]);
            t = add2(a2.y, c01) & ABSM; acc[q][0] = fma2(t, vv.y, acc[q][0]);
            t = add2(a2.x, c10) & ABSM; acc[q][1] = fma2(t, vv.x, acc[q][1]);
            t = add2(a2.y, c11) & ABSM; acc[q][1] = fma2(t, vv.y, acc[q][1]);
        }
    }
    __syncthreads();   // sq_s ready

    int mk0 = mask[b * L + c0];
    int mk1 = mask[b * L + c0 + 1];
    float sc0 = hsum2(lin0), sc1 = hsum2(lin1);
    const float NEG_INF = __int_as_float(0xff800000u);
    #pragma unroll
    for (int q = 0; q < 4; q++) {
        int qq = tg * 4 + q;
        float base = sq_s[qq];
        float s0 = 0.505f * (base + sc0) + 0.495f * hsum2(acc[q][0]);
        float s1 = 0.505f * (base + sc1) + 0.495f * hsum2(acc[q][1]);
        if (mk0 == 0) s0 = NEG_INF;
        if (mk1 == 0) s1 = NEG_INF;
        *(float2*)&S[qq][c0] = make_float2(s0, s1);
    }
    __syncthreads();

    // softmax: warp w reduces row q = w
    {
        float m = NEG_INF;
        #pragma unroll
        for (int j = 0; j < 8; j++) m = fmaxf(m, S[w][lane + 32 * j]);
        #pragma unroll
        for (int off = 16; off; off >>= 1) m = fmaxf(m, __shfl_xor_sync(0xffffffffu, m, off));
        float ssum = 0.f;
        #pragma unroll
        for (int j = 0; j < 8; j++) {
            float e = __expf(S[w][lane + 32 * j] - m);
            S[w][lane + 32 * j] = e;
            ssum += e;
        }
        #pragma unroll
        for (int off = 16; off; off >>= 1) ssum += __shfl_xor_sync(0xffffffffu, ssum, off);
        if (lane == 0) inv_s[w] = 1.f / ssum;
    }
    __syncthreads();

    // scale + write attn
    #pragma unroll
    for (int q = 0; q < 8; q++) {
        float a = S[q][tid] * inv_s[q];
        S[q][tid] = a;
        attn[(b * L + q0 + q) * L + tid] = a;
    }
    __syncthreads();

    // AV: out[q][h=tid] = sum_c attn[q][c] * ctx[b][c][h], 4 c per iter
    ull av[8];
    #pragma unroll
    for (int q = 0; q < 8; q++) av[q] = 0ULL;
    const float* cb = ctx + b * (L * H) + tid;
    #pragma unroll 2
    for (int cg = 0; cg < 64; cg++) {
        float x0 = cb[(4 * cg + 0) * H];
        float x1 = cb[(4 * cg + 1) * H];
        float x2 = cb[(4 * cg + 2) * H];
        float x3 = cb[(4 * cg + 3) * H];
        ull cc01 = pack2(x0, x1);
        ull cc23 = pack2(x2, x3);
        #pragma unroll
        for (int q = 0; q < 8; q++) {
            ulonglong2 a = *(const ulonglong2*)&S[q][cg << 2];
            av[q] = fma2(a.x, cc01, av[q]);
            av[q] = fma2(a.y, cc23, av[q]);
        }
    }
    #pragma unroll
    for (int q = 0; q < 8; q++) {
        attn_out[(b * L + q0 + q) * H + tid] = hsum2(av[q]);
    }
}

extern "C" void kernel_launch(void* const* d_in, const int* in_sizes, int n_in,
                              void* d_out, int out_size)
{
    const float* query   = (const float*)d_in[0];
    const float* context = (const float*)d_in[1];
    const int*   mask    = (const int*)d_in[2];
    const float* w       = (const float*)d_in[3];
    const float* bias    = (const float*)d_in[4];
    const float* sw      = (const float*)d_in[5];

    float* out = (float*)d_out;
    float* attn_out = out;                      // (B, Lq, H)
    float* attn     = out + Bdim * L * H;       // (B, Lq, Lc)

    dim3 pgrid(64, 4, 2);
    proj_kernel<<<pgrid, 256>>>(query, context, w, bias);
    score_kernel<<<512, 256>>>(context, mask, sw, attn_out, attn);
}

// round 5
// speedup vs baseline: 1.2829x; 1.0404x over previous
#include <cuda_runtime.h>
#include <cstdint>

#define Bdim 16
#define L 256
#define H 256

typedef unsigned long long ull;

// Scratch (device globals: allocation-free)
__device__ __align__(16) float g_A[Bdim * L * H];    // A[b][q][o] row-major (= query @ Wq^T)
__device__ __align__(16) float g_Ct2[Bdim * L * H];  // [b][op=o/2][c][2] : C[b][c][o], C = context @ Wc^T + bias

// ---------------- f32x2 helpers ----------------
__device__ __forceinline__ ull fma2(ull a, ull b, ull c) {
    ull d; asm("fma.rn.f32x2 %0, %1, %2, %3;" : "=l"(d) : "l"(a), "l"(b), "l"(c)); return d;
}
__device__ __forceinline__ ull add2(ull a, ull b) {
    ull d; asm("add.rn.f32x2 %0, %1, %2;" : "=l"(d) : "l"(a), "l"(b)); return d;
}
__device__ __forceinline__ ull pack2(float lo, float hi) {
    ull d; asm("mov.b64 %0, {%1, %2};" : "=l"(d) : "f"(lo), "f"(hi)); return d;
}
__device__ __forceinline__ float2 unpack2(ull a) {
    float2 r; asm("mov.b64 {%0, %1}, %2;" : "=f"(r.x), "=f"(r.y) : "l"(a)); return r;
}
__device__ __forceinline__ float hsum2(ull a) { float2 r = unpack2(a); return r.x + r.y; }

// ---------------- Projection GEMM (unchanged, known good) ----------------
#define KC 32
#define PAD 70

__global__ __launch_bounds__(256) void proj_kernel(
    const float* __restrict__ query, const float* __restrict__ context,
    const float* __restrict__ W, const float* __restrict__ bias)
{
    __shared__ __align__(16) float smem_all[2 * KC * PAD];
    float (*As)[PAD] = (float(*)[PAD])smem_all;              // As[k][m]
    float (*Bs)[PAD] = (float(*)[PAD])(smem_all + KC * PAD); // Bs[k][n]

    const int tid = threadIdx.x;
    const int tx = tid & 15;          // n quad
    const int ty = tid >> 4;          // m quad
    const int row0 = blockIdx.x * 64;
    const int n0 = blockIdx.y * 64;
    const int which = blockIdx.z;

    const float* X = which ? context : query;
    const float* Wbase = W + (which ? H : 0);   // row stride 2H

    ull acc[4][2];
    #pragma unroll
    for (int i = 0; i < 4; i++) { acc[i][0] = 0ULL; acc[i][1] = 0ULL; }

    for (int kc = 0; kc < H; kc += KC) {
        #pragma unroll
        for (int it = 0; it < 8; it++) {
            int i = it * 256 + tid;
            int r = i >> 5, k = i & 31;
            As[k][r] = X[(row0 + r) * H + kc + k];
        }
        #pragma unroll
        for (int it = 0; it < 8; it++) {
            int i = it * 256 + tid;
            int n = i >> 5, k = i & 31;
            Bs[k][n] = Wbase[(n0 + n) * (2 * H) + kc + k];
        }
        __syncthreads();

        #pragma unroll
        for (int k = 0; k < KC; k++) {
            ull b01 = *(const ull*)&Bs[k][tx * 4];
            ull b23 = *(const ull*)&Bs[k][tx * 4 + 2];
            #pragma unroll
            for (int i = 0; i < 4; i++) {
                float a = As[k][ty * 4 + i];
                ull a2 = pack2(a, a);
                acc[i][0] = fma2(a2, b01, acc[i][0]);
                acc[i][1] = fma2(a2, b23, acc[i][1]);
            }
        }
        __syncthreads();
    }

    if (which == 0) {
        #pragma unroll
        for (int i = 0; i < 4; i++) {
            float2 p0 = unpack2(acc[i][0]);
            float2 p1 = unpack2(acc[i][1]);
            float4 v = make_float4(p0.x, p0.y, p1.x, p1.y);
            *(float4*)&g_A[(row0 + ty * 4 + i) * H + n0 + tx * 4] = v;
        }
    } else {
        float bv0 = bias[n0 + tx * 4 + 0];
        float bv1 = bias[n0 + tx * 4 + 1];
        float bv2v = bias[n0 + tx * 4 + 2];
        float bv3 = bias[n0 + tx * 4 + 3];
        float* T = smem_all;  // 64 x 66 tile
        #pragma unroll
        for (int i = 0; i < 4; i++) {
            float2 p0 = unpack2(acc[i][0]);
            float2 p1 = unpack2(acc[i][1]);
            int m = ty * 4 + i;
            T[m * 66 + tx * 4 + 0] = p0.x + bv0;
            T[m * 66 + tx * 4 + 1] = p0.y + bv1;
            T[m * 66 + tx * 4 + 2] = p1.x + bv2v;
            T[m * 66 + tx * 4 + 3] = p1.y + bv3;
        }
        __syncthreads();
        const int b = row0 >> 8;
        const int c0 = row0 & 255;
        float2* dst = (float2*)g_Ct2;
        #pragma unroll
        for (int it = 0; it < 8; it++) {
            int e = it * 256 + tid;
            int m = e & 63;        // c within tile
            int np = e >> 6;       // o-pair within tile (0..31)
            float v0 = T[m * 66 + 2 * np];
            float v1 = T[m * 66 + 2 * np + 1];
            dst[(b * 128 + (n0 >> 1) + np) * 256 + (c0 + m)] = make_float2(v0, v1);
        }
    }
}

// ---------------- Fused score + softmax + AV ----------------
// 128 threads, block = (b, q0..q0+7) x 256 c.
// tg = tid>>6 picks q-quad (q0..q0+3 or q0+4..q0+7), ct = tid&63 picks c-quad 4ct..4ct+3.
// All LDS in the hot loop are warp-uniform broadcasts; C comes in as 4x LDG.128.
__global__ __launch_bounds__(128, 6) void score_kernel(
    const float* __restrict__ ctx, const int* __restrict__ mask,
    const float* __restrict__ sw, float* __restrict__ attn_out, float* __restrict__ attn)
{
    __shared__ __align__(16) float Aq[8][256];
    __shared__ __align__(16) float S[8][256];
    __shared__ __align__(16) ull v2s[128];
    __shared__ float sq_s[8], inv_s[8];

    const int tid = threadIdx.x;
    const int lane = tid & 31;
    const int w = tid >> 5;
    const int b = blockIdx.x >> 5;
    const int q0 = (blockIdx.x & 31) << 3;
    const int tg = tid >> 6;          // q-quad select
    const int ct = tid & 63;          // c-quad select
    const int c0 = ct << 2;

    v2s[tid] = pack2(sw[2 * tid], sw[2 * tid + 1]);
    #pragma unroll
    for (int it = 0; it < 4; it++) {
        int fi = it * 128 + tid;
        int q = fi >> 6, o = (fi & 63) << 2;
        *(float4*)&Aq[q][o] = *(const float4*)&g_A[(b * L + q0 + q) * H + o];
    }
    __syncthreads();

    // sq[q] = sum_o v[o] * A[q][o]   (warp w handles q = 2w, 2w+1)
    #pragma unroll
    for (int rq = 0; rq < 2; rq++) {
        int q = 2 * w + rq;
        float s = 0.f;
        #pragma unroll
        for (int j = 0; j < 8; j++) s += sw[lane + 32 * j] * Aq[q][lane + 32 * j];
        #pragma unroll
        for (int off = 16; off; off >>= 1) s += __shfl_xor_sync(0xffffffffu, s, off);
        if (lane == 0) sq_s[q] = s;
    }

    // main score loop: per og (4 o-values): 4 LDG.128 (C), 4+1 broadcast LDS.128
    ull acc[4][4];
    #pragma unroll
    for (int q = 0; q < 4; q++)
        #pragma unroll
        for (int j = 0; j < 4; j++) acc[q][j] = 0ULL;
    ull lin[4] = {0ULL, 0ULL, 0ULL, 0ULL};
    const float4* Cp = (const float4*)g_Ct2 + b * (128 * 128) + 2 * ct;
    const ull ABSM = 0x7FFFFFFF7FFFFFFFULL;
    const int tg4 = tg * 4;

    #pragma unroll 2
    for (int og = 0; og < 64; og++) {
        float4 X0a = Cp[og * 256];
        float4 X0b = Cp[og * 256 + 1];
        float4 X1a = Cp[og * 256 + 128];
        float4 X1b = Cp[og * 256 + 129];
        ulonglong2 vv = *(const ulonglong2*)&v2s[2 * og];
        ull e0 = pack2(X0a.x, X0a.y), e1 = pack2(X0a.z, X0a.w);
        ull e2 = pack2(X0b.x, X0b.y), e3 = pack2(X0b.z, X0b.w);
        ull f0 = pack2(X1a.x, X1a.y), f1 = pack2(X1a.z, X1a.w);
        ull f2 = pack2(X1b.x, X1b.y), f3 = pack2(X1b.z, X1b.w);
        lin[0] = fma2(e0, vv.x, lin[0]); lin[0] = fma2(f0, vv.y, lin[0]);
        lin[1] = fma2(e1, vv.x, lin[1]); lin[1] = fma2(f1, vv.y, lin[1]);
        lin[2] = fma2(e2, vv.x, lin[2]); lin[2] = fma2(f2, vv.y, lin[2]);
        lin[3] = fma2(e3, vv.x, lin[3]); lin[3] = fma2(f3, vv.y, lin[3]);
        #pragma unroll
        for (int q = 0; q < 4; q++) {
            ulonglong2 a2 = *(const ulonglong2*)&Aq[tg4 + q][og << 2];
            ull t;
            t = add2(a2.x, e0) & ABSM; acc[q][0] = fma2(t, vv.x, acc[q][0]);
            t = add2(a2.y, f0) & ABSM; acc[q][0] = fma2(t, vv.y, acc[q][0]);
            t = add2(a2.x, e1) & ABSM; acc[q][1] = fma2(t, vv.x, acc[q][1]);
            t = add2(a2.y, f1) & ABSM; acc[q][1] = fma2(t, vv.y, acc[q][1]);
            t = add2(a2.x, e2) & ABSM; acc[q][2] = fma2(t, vv.x, acc[q][2]);
            t = add2(a2.y, f2) & ABSM; acc[q][2] = fma2(t, vv.y, acc[q][2]);
            t = add2(a2.x, e3) & ABSM; acc[q][3] = fma2(t, vv.x, acc[q][3]);
            t = add2(a2.y, f3) & ABSM; acc[q][3] = fma2(t, vv.y, acc[q][3]);
        }
    }
    __syncthreads();   // sq_s ready

    int4 mk = *(const int4*)&mask[b * L + c0];
    float sc0 = hsum2(lin[0]), sc1 = hsum2(lin[1]);
    float sc2 = hsum2(lin[2]), sc3 = hsum2(lin[3]);
    const float NEG_INF = __int_as_float(0xff800000u);
    #pragma unroll
    for (int q = 0; q < 4; q++) {
        int qq = tg4 + q;
        float base = sq_s[qq];
        float s0 = 0.505f * (base + sc0) + 0.495f * hsum2(acc[q][0]);
        float s1 = 0.505f * (base + sc1) + 0.495f * hsum2(acc[q][1]);
        float s2 = 0.505f * (base + sc2) + 0.495f * hsum2(acc[q][2]);
        float s3 = 0.505f * (base + sc3) + 0.495f * hsum2(acc[q][3]);
        if (mk.x == 0) s0 = NEG_INF;
        if (mk.y == 0) s1 = NEG_INF;
        if (mk.z == 0) s2 = NEG_INF;
        if (mk.w == 0) s3 = NEG_INF;
        *(float4*)&S[qq][c0] = make_float4(s0, s1, s2, s3);
    }
    __syncthreads();

    // softmax: warp w reduces rows q = 2w, 2w+1
    #pragma unroll
    for (int rq = 0; rq < 2; rq++) {
        int q = 2 * w + rq;
        float m = NEG_INF;
        #pragma unroll
        for (int j = 0; j < 8; j++) m = fmaxf(m, S[q][lane + 32 * j]);
        #pragma unroll
        for (int off = 16; off; off >>= 1) m = fmaxf(m, __shfl_xor_sync(0xffffffffu, m, off));
        float ssum = 0.f;
        #pragma unroll
        for (int j = 0; j < 8; j++) {
            float e = __expf(S[q][lane + 32 * j] - m);
            S[q][lane + 32 * j] = e;
            ssum += e;
        }
        #pragma unroll
        for (int off = 16; off; off >>= 1) ssum += __shfl_xor_sync(0xffffffffu, ssum, off);
        if (lane == 0) inv_s[q] = 1.f / ssum;
    }
    __syncthreads();

    // scale + write attn (float4)
    #pragma unroll
    for (int it = 0; it < 4; it++) {
        int fi = it * 128 + tid;
        int q = fi >> 6, cc = (fi & 63) << 2;
        float4 vS = *(float4*)&S[q][cc];
        float iv = inv_s[q];
        vS.x *= iv; vS.y *= iv; vS.z *= iv; vS.w *= iv;
        *(float4*)&S[q][cc] = vS;
        *(float4*)&attn[(b * L + q0 + q) * L + cc] = vS;
    }
    __syncthreads();

    // AV: out[q][h] for h = tid and tid+128; S reads are warp-broadcast
    ull av[8][2];
    #pragma unroll
    for (int q = 0; q < 8; q++) { av[q][0] = 0ULL; av[q][1] = 0ULL; }
    const float* cb = ctx + b * (L * H) + tid;
    #pragma unroll 2
    for (int cg = 0; cg < 64; cg++) {
        float y00 = cb[(4 * cg + 0) * H], y01 = cb[(4 * cg + 1) * H];
        float y02 = cb[(4 * cg + 2) * H], y03 = cb[(4 * cg + 3) * H];
        float y10 = cb[(4 * cg + 0) * H + 128], y11 = cb[(4 * cg + 1) * H + 128];
        float y12 = cb[(4 * cg + 2) * H + 128], y13 = cb[(4 * cg + 3) * H + 128];
        ull p0a = pack2(y00, y01), p0b = pack2(y02, y03);
        ull p1a = pack2(y10, y11), p1b = pack2(y12, y13);
        #pragma unroll
        for (int q = 0; q < 8; q++) {
            ulonglong2 a = *(const ulonglong2*)&S[q][cg << 2];
            av[q][0] = fma2(a.x, p0a, av[q][0]);
            av[q][0] = fma2(a.y, p0b, av[q][0]);
            av[q][1] = fma2(a.x, p1a, av[q][1]);
            av[q][1] = fma2(a.y, p1b, av[q][1]);
        }
    }
    #pragma unroll
    for (int q = 0; q < 8; q++) {
        attn_out[(b * L + q0 + q) * H + tid] = hsum2(av[q][0]);
        attn_out[(b * L + q0 + q) * H + tid + 128] = hsum2(av[q][1]);
    }
}

extern "C" void kernel_launch(void* const* d_in, const int* in_sizes, int n_in,
                              void* d_out, int out_size)
{
    const float* query   = (const float*)d_in[0];
    const float* context = (const float*)d_in[1];
    const int*   mask    = (const int*)d_in[2];
    const float* w       = (const float*)d_in[3];
    const float* bias    = (const float*)d_in[4];
    const float* sw      = (const float*)d_in[5];

    float* out = (float*)d_out;
    float* attn_out = out;                      // (B, Lq, H)
    float* attn     = out + Bdim * L * H;       // (B, Lq, Lc)

    dim3 pgrid(64, 4, 2);
    proj_kernel<<<pgrid, 256>>>(query, context, w, bias);
    score_kernel<<<512, 128>>>(context, mask, sw, attn_out, attn);
}